// round 8
// baseline (speedup 1.0000x reference)
#include <cuda_runtime.h>
#include <math.h>

#define NPT 8192
#define L2E 1.4426950408889634f
#define LN2 0.6931471805599453f
#define K0  (-13.0f)                 // log2(1/8192), exact

#define TILE 1024
#define RPW 8
#define THREADS 128
#define ROWS_CTA 32                   // 4 warps * 8 rows
#define CTA_PER_PROB 256              // NPT / ROWS_CTA
#define NCHUNK 256                    // NPT / 32
#define NTILE 8                       // NPT / TILE
#define THRESH (-35.0f)
#define SC_DENSE 16.0f

typedef unsigned long long u64;

// Persistent scratch (no allocation anywhere)
__device__ u64    d_keys[2][NPT];
__device__ float4 d_pts[2][NPT];              // sorted: (x,y,z,|p|^2/2); 0=X,1=Y
__device__ float4 d_bLo[2][NCHUNK], d_bHi[2][NCHUNK];
__device__ float  d_du[2][4][NPT];            // [parity][f,g,pp,qq][sorted i]
__device__ float  d_ls[2][4][NPT];            // row lse (log2 units)
__device__ float  d_sU[2][4][NCHUNK];         // per-chunk max of dual

__device__ __forceinline__ float ex2(float x) {
    float y; asm("ex2.approx.f32 %0, %1;" : "=f"(y) : "f"(x)); return y;
}

__device__ __forceinline__ unsigned expand10(unsigned v) {
    v &= 1023u;
    v = (v | (v << 16)) & 0x030000FFu;
    v = (v | (v << 8))  & 0x0300F00Fu;
    v = (v | (v << 4))  & 0x030C30C3u;
    v = (v | (v << 2))  & 0x09249249u;
    return v;
}

__global__ void key_kernel(const float* __restrict__ X, const float* __restrict__ Y) {
    int i = blockIdx.x * blockDim.x + threadIdx.x;
    if (i >= NPT) return;
    const float* P[2] = {X, Y};
#pragma unroll
    for (int s = 0; s < 2; s++) {
        float x0 = P[s][3*i], x1 = P[s][3*i+1], x2 = P[s][3*i+2];
        unsigned qx = min(1023, max(0, (int)(x0 * 1024.f)));
        unsigned qy = min(1023, max(0, (int)(x1 * 1024.f)));
        unsigned qz = min(1023, max(0, (int)(x2 * 1024.f)));
        u64 code = expand10(qx) | (expand10(qy) << 1) | (expand10(qz) << 2);
        d_keys[s][i] = (code << 13) | (u64)i;
    }
}

__global__ void sort_kernel() {
    u64* keys = d_keys[blockIdx.x];
    for (int k = 2; k <= NPT; k <<= 1) {
        for (int j = k >> 1; j > 0; j >>= 1) {
            for (int t = threadIdx.x; t < NPT; t += blockDim.x) {
                int ixj = t ^ j;
                if (ixj > t) {
                    u64 a = keys[t], b = keys[ixj];
                    bool up = ((t & k) == 0);
                    if (up ? (a > b) : (a < b)) { keys[t] = b; keys[ixj] = a; }
                }
            }
            __syncthreads();
        }
    }
}

__global__ void build_kernel(const float* __restrict__ X, const float* __restrict__ Y) {
    int i = blockIdx.x * blockDim.x + threadIdx.x;
    if (i >= NPT) return;
    const float* P[2] = {X, Y};
#pragma unroll
    for (int s = 0; s < 2; s++) {
        int idx = (int)(d_keys[s][i] & 8191u);
        float x0 = P[s][3*idx], x1 = P[s][3*idx+1], x2 = P[s][3*idx+2];
        d_pts[s][i] = make_float4(x0, x1, x2, 0.5f * (x0*x0 + x1*x1 + x2*x2));
    }
#pragma unroll
    for (int p = 0; p < 4; p++) {
        d_du[0][p][i] = 0.f;
        d_ls[0][p][i] = K0 + 0.6f;
        if (i < NCHUNK) d_sU[0][p][i] = 0.f;
    }
}

__global__ void bbox_kernel() {
    int t = blockIdx.x * blockDim.x + threadIdx.x;
    if (t >= 2 * NCHUNK) return;
    int s = t >> 8, c = t & 255;
    float lx = 1e30f, ly = 1e30f, lz = 1e30f, hx = -1e30f, hy = -1e30f, hz = -1e30f;
#pragma unroll 8
    for (int j = 0; j < 32; j++) {
        float4 p = d_pts[s][c * 32 + j];
        lx = fminf(lx, p.x); ly = fminf(ly, p.y); lz = fminf(lz, p.z);
        hx = fmaxf(hx, p.x); hy = fmaxf(hy, p.y); hz = fmaxf(hz, p.z);
    }
    d_bLo[s][c] = make_float4(lx, ly, lz, 0.f);
    d_bHi[s][c] = make_float4(hx, hy, hz, 0.f);
}

// ---------------------------------------------------------------------------
// DENSE variant (sc <= 16): no M subtraction (range-proof), no pruning.
// Inner loop = 3 FFMA + 1 FADD + 1 MUFU per element (at the MUFU floor).
// ---------------------------------------------------------------------------
__global__ void __launch_bounds__(THREADS)
phase_dense(float eps, int avg, int par) {
    __shared__ float4 tile[TILE];
    __shared__ float  shRes[ROWS_CTA];

    int prob = blockIdx.x >> 8;
    int rb   = blockIdx.x & (CTA_PER_PROB - 1);

    int cset = (prob == 1 || prob == 2) ? 0 : 1;
    int rset = (prob == 0 || prob == 2) ? 0 : 1;
    const float4* __restrict__ cpts = d_pts[cset];
    const float4* __restrict__ rpts = d_pts[rset];
    int didx = (prob == 0) ? 1 : (prob == 1) ? 0 : prob;
    const float* __restrict__ cdual  = d_du[par][didx];
    const float* __restrict__ oldpot = d_du[par][prob];
    float* __restrict__ outpot       = d_du[par ^ 1][prob];
    float* __restrict__ outlse       = d_ls[par ^ 1][prob];

    int warp = threadIdx.x >> 5;
    int lane = threadIdx.x & 31;
    int row0 = rb * ROWS_CTA + warp * RPW;

    float sc = L2E / eps;

    float a0[RPW], a1[RPW], a2[RPW], S[RPW];
#pragma unroll
    for (int r = 0; r < RPW; r++) {
        float4 p = rpts[row0 + r];
        a0[r] = p.x * sc; a1[r] = p.y * sc; a2[r] = p.z * sc;
        S[r] = 0.f;
    }

    for (int tb = 0; tb < NPT; tb += TILE) {
        __syncthreads();
        for (int j = threadIdx.x; j < TILE; j += THREADS) {
            float4 p = cpts[tb + j];
            p.w = fmaf(sc, cdual[tb + j] - p.w, K0);   // column bias cb_j
            tile[j] = p;
        }
        __syncthreads();
#pragma unroll 4
        for (int k = 0; k < TILE / 32; k++) {
            float4 cc = tile[k * 32 + lane];
#pragma unroll
            for (int r = 0; r < RPW; r++) {
                float t = fmaf(a0[r], cc.x, fmaf(a1[r], cc.y, fmaf(a2[r], cc.z, cc.w)));
                S[r] += ex2(t);
            }
        }
    }

#pragma unroll
    for (int r = 0; r < RPW; r++)
#pragma unroll
        for (int o = 16; o; o >>= 1)
            S[r] += __shfl_xor_sync(0xffffffffu, S[r], o);

    float lse[RPW];
    int bad = 0;
#pragma unroll
    for (int r = 0; r < RPW; r++) {
        if (!(S[r] > 1e-35f && S[r] < 1e35f)) bad = 1;
        lse[r] = log2f(S[r]);
    }

    if (__any_sync(0xffffffffu, bad)) {
        // cold exact fallback: warp-local online softmax
#pragma unroll 1
        for (int r = 0; r < RPW; r++) {
            float4 q = rpts[row0 + r];
            float b0 = q.x * sc, b1 = q.y * sc, b2 = q.z * sc;
            float mm = -3.0e38f, ss = 0.f;
            for (int j = lane; j < NPT; j += 32) {
                float4 p = cpts[j];
                float t = fmaf(b0, p.x, fmaf(b1, p.y,
                          fmaf(b2, p.z, fmaf(sc, cdual[j] - p.w, K0))));
                float mn = fmaxf(mm, t);
                ss = fmaf(ss, ex2(mm - mn), ex2(t - mn));
                mm = mn;
            }
            for (int o = 16; o; o >>= 1) {
                float mo = __shfl_xor_sync(0xffffffffu, mm, o);
                float so = __shfl_xor_sync(0xffffffffu, ss, o);
                float mn = fmaxf(mm, mo);
                ss = ss * ex2(mm - mn) + so * ex2(mo - mn);
                mm = mn;
            }
            lse[r] = mm + log2f(ss);
        }
    }

    float resv[RPW];
#pragma unroll
    for (int r = 0; r < RPW; r++) {
        int row = row0 + r;
        float res = rpts[row].w - eps * LN2 * lse[r];
        resv[r] = avg ? 0.5f * (oldpot[row] + res) : res;
    }
    if (lane == 0) {
#pragma unroll
        for (int r = 0; r < RPW; r++) {
            int row = row0 + r;
            outpot[row] = resv[r];
            outlse[row] = lse[r];
            shRes[warp * RPW + r] = resv[r];
        }
    }
    __syncthreads();
    if (threadIdx.x < 32) {
        float v = shRes[threadIdx.x];
#pragma unroll
        for (int o = 16; o; o >>= 1)
            v = fmaxf(v, __shfl_xor_sync(0xffffffffu, v, o));
        if (threadIdx.x == 0) d_sU[par ^ 1][prob][rb] = v;
    }
}

// ---------------------------------------------------------------------------
// PRUNED variant (sc > 16): predicted M + prologue-computed per-warp skip masks.
// ---------------------------------------------------------------------------
__global__ void __launch_bounds__(THREADS)
phase_pruned(float eps, float ratio_inv, int avg, int par) {
    __shared__ float4   tile[TILE];
    __shared__ unsigned smask[4][NTILE];
    __shared__ float    shRes[ROWS_CTA];

    int prob = blockIdx.x >> 8;
    int rb   = blockIdx.x & (CTA_PER_PROB - 1);

    int cset = (prob == 1 || prob == 2) ? 0 : 1;
    int rset = (prob == 0 || prob == 2) ? 0 : 1;
    const float4* __restrict__ cpts = d_pts[cset];
    const float4* __restrict__ rpts = d_pts[rset];
    int didx = (prob == 0) ? 1 : (prob == 1) ? 0 : prob;
    const float* __restrict__ cdual  = d_du[par][didx];
    const float* __restrict__ oldpot = d_du[par][prob];
    const float* __restrict__ oldlse = d_ls[par][prob];
    const float* __restrict__ sUraw  = d_sU[par][didx];
    float* __restrict__ outpot       = d_du[par ^ 1][prob];
    float* __restrict__ outlse       = d_ls[par ^ 1][prob];

    int warp = threadIdx.x >> 5;
    int lane = threadIdx.x & 31;
    int row0 = rb * ROWS_CTA + warp * RPW;

    float sc  = L2E / eps;
    float hsc = 0.5f * sc;

    float a0[RPW], a1[RPW], a2[RPW], NM[RPW], S[RPW];
    float rlx = 1e30f, rly = 1e30f, rlz = 1e30f;
    float rhx = -1e30f, rhy = -1e30f, rhz = -1e30f;
    float CRM = -1e30f;
#pragma unroll
    for (int r = 0; r < RPW; r++) {
        float4 p = rpts[row0 + r];
        a0[r] = p.x * sc; a1[r] = p.y * sc; a2[r] = p.z * sc;
        float M = fmaf(oldlse[row0 + r] - K0, ratio_inv, K0 + 4.0f);
        NM[r] = -M;
        S[r] = 0.f;
        rlx = fminf(rlx, p.x); rly = fminf(rly, p.y); rlz = fminf(rlz, p.z);
        rhx = fmaxf(rhx, p.x); rhy = fmaxf(rhy, p.y); rhz = fmaxf(rhz, p.z);
        CRM = fmaxf(CRM, sc * p.w - M);
    }

    // prologue: lane-parallel chunk tests -> 256-bit mask per warp
#pragma unroll
    for (int t8 = 0; t8 < NTILE; t8++) {
        int c = t8 * 32 + lane;
        float4 lo = d_bLo[cset][c];
        float4 hi = d_bHi[cset][c];
        float dx = fmaxf(0.f, fmaxf(lo.x - rhx, rlx - hi.x));
        float dy = fmaxf(0.f, fmaxf(lo.y - rhy, rly - hi.y));
        float dz = fmaxf(0.f, fmaxf(lo.z - rhz, rlz - hi.z));
        float mind2 = fmaf(dx, dx, fmaf(dy, dy, dz * dz));
        float UB = CRM + K0 + sc * sUraw[c] - hsc * mind2;
        unsigned b = __ballot_sync(0xffffffffu, UB >= THRESH);
        if (lane == 0) smask[warp][t8] = b;
    }
    __syncthreads();

    for (int t8 = 0; t8 < NTILE; t8++) {
        unsigned need = smask[0][t8] | smask[1][t8] | smask[2][t8] | smask[3][t8];
        if (!need) continue;
        __syncthreads();
        int tb = t8 * TILE;
        for (int j = threadIdx.x; j < TILE; j += THREADS) {
            float4 p = cpts[tb + j];
            p.w = fmaf(sc, cdual[tb + j] - p.w, K0);
            tile[j] = p;
        }
        __syncthreads();

        unsigned mw = smask[warp][t8];
        while (mw) {
            int k = __ffs(mw) - 1;
            mw &= mw - 1;
            float4 cc = tile[k * 32 + lane];
#pragma unroll
            for (int r = 0; r < RPW; r++) {
                float t = fmaf(a0[r], cc.x,
                          fmaf(a1[r], cc.y,
                          fmaf(a2[r], cc.z, cc.w + NM[r])));
                S[r] += ex2(t);
            }
        }
    }

#pragma unroll
    for (int r = 0; r < RPW; r++)
#pragma unroll
        for (int o = 16; o; o >>= 1)
            S[r] += __shfl_xor_sync(0xffffffffu, S[r], o);

    float lse[RPW];
    int bad = 0;
#pragma unroll
    for (int r = 0; r < RPW; r++) {
        if (!(S[r] > 1e-25f && S[r] < 1e25f)) bad = 1;
        lse[r] = -NM[r] + log2f(S[r]);
    }

    if (__any_sync(0xffffffffu, bad)) {
#pragma unroll 1
        for (int r = 0; r < RPW; r++) {
            float4 q = rpts[row0 + r];
            float b0 = q.x * sc, b1 = q.y * sc, b2 = q.z * sc;
            float mm = -3.0e38f, ss = 0.f;
            for (int j = lane; j < NPT; j += 32) {
                float4 p = cpts[j];
                float t = fmaf(b0, p.x, fmaf(b1, p.y,
                          fmaf(b2, p.z, fmaf(sc, cdual[j] - p.w, K0))));
                float mn = fmaxf(mm, t);
                ss = fmaf(ss, ex2(mm - mn), ex2(t - mn));
                mm = mn;
            }
            for (int o = 16; o; o >>= 1) {
                float mo = __shfl_xor_sync(0xffffffffu, mm, o);
                float so = __shfl_xor_sync(0xffffffffu, ss, o);
                float mn = fmaxf(mm, mo);
                ss = ss * ex2(mm - mn) + so * ex2(mo - mn);
                mm = mn;
            }
            lse[r] = mm + log2f(ss);
        }
    }

    float resv[RPW];
#pragma unroll
    for (int r = 0; r < RPW; r++) {
        int row = row0 + r;
        float res = rpts[row].w - eps * LN2 * lse[r];
        resv[r] = avg ? 0.5f * (oldpot[row] + res) : res;
    }
    if (lane == 0) {
#pragma unroll
        for (int r = 0; r < RPW; r++) {
            int row = row0 + r;
            outpot[row] = resv[r];
            outlse[row] = lse[r];
            shRes[warp * RPW + r] = resv[r];
        }
    }
    __syncthreads();
    if (threadIdx.x < 32) {
        float v = shRes[threadIdx.x];
#pragma unroll
        for (int o = 16; o; o >>= 1)
            v = fmaxf(v, __shfl_xor_sync(0xffffffffu, v, o));
        if (threadIdx.x == 0) d_sU[par ^ 1][prob][rb] = v;
    }
}

__global__ void reduce_kernel(float* out, int out_size) {
    __shared__ double sh[256];
    double s = 0.0;
    for (int i = threadIdx.x; i < NPT; i += 256)
        s += (double)(d_du[1][0][i] - d_du[1][2][i])
           + (double)(d_du[1][1][i] - d_du[1][3][i]);
    sh[threadIdx.x] = s;
    __syncthreads();
    for (int o = 128; o > 0; o >>= 1) {
        if (threadIdx.x < o) sh[threadIdx.x] += sh[threadIdx.x + o];
        __syncthreads();
    }
    if (threadIdx.x == 0) {
        float v = (float)(sh[0] / (double)NPT);
        for (int k = 0; k < out_size; k++) out[k] = v;
    }
}

extern "C" void kernel_launch(void* const* d_in, const int* in_sizes, int n_in,
                              void* d_out, int out_size) {
    const float* X = (const float*)d_in[0];
    const float* Y = (const float*)d_in[1];

    double sched[96];
    int ns = 0;
    double e      = pow(2.0, 2.0);
    double target = pow(0.01, 2.0);
    double ratio  = pow(0.9, 2.0);
    while (e > target) { sched[ns++] = e; e *= ratio; }

    key_kernel<<<NPT / 256, 256>>>(X, Y);
    sort_kernel<<<2, 1024>>>();
    build_kernel<<<NPT / 256, 256>>>(X, Y);
    bbox_kernel<<<2, 256>>>();

    double eps_prev = sched[0];
    for (int p = 0; p <= ns + 1; p++) {
        double eps; int avg;
        if (p == 0)       { eps = sched[0];     avg = 0; }
        else if (p <= ns) { eps = sched[p - 1]; avg = 1; }
        else              { eps = target;       avg = 0; }
        float sc = (float)((double)L2E / eps);
        if (sc <= SC_DENSE)
            phase_dense<<<4 * CTA_PER_PROB, THREADS>>>((float)eps, avg, p & 1);
        else {
            float ratio_inv = (float)(eps_prev / eps);
            phase_pruned<<<4 * CTA_PER_PROB, THREADS>>>((float)eps, ratio_inv, avg, p & 1);
        }
        eps_prev = eps;
    }
    reduce_kernel<<<1, 256>>>((float*)d_out, out_size);
}

// round 11
// speedup vs baseline: 1.3167x; 1.3167x over previous
#include <cuda_runtime.h>
#include <math.h>

#define NPT 8192
#define L2E 1.4426950408889634f
#define LN2 0.6931471805599453f
#define K0  (-13.0f)                 // log2(1/8192), exact

#define TILE 1024
#define RPW 8
#define THREADS 128
#define ROWS_CTA 32                   // 4 warps * 8 rows
#define CTA_PER_PROB 256              // NPT / ROWS_CTA
#define NCHUNK 256                    // NPT / 32
#define NTILE 8                       // NPT / TILE
#define THRESH (-46.0f)
#define SC_CTAM 64.0f

typedef unsigned long long u64;

// Persistent scratch (no allocation anywhere)
__device__ u64    d_keys[2][NPT];
__device__ float4 d_pts[2][NPT];              // sorted: (x,y,z,|p|^2/2); 0=X,1=Y
__device__ float4 d_bLo[2][NCHUNK], d_bHi[2][NCHUNK];
__device__ float  d_du[2][4][NPT];            // [parity][f,g,pp,qq][sorted i]
__device__ float  d_ls[2][4][NPT];            // row lse (log2 units)
__device__ float  d_sU[2][4][NCHUNK];         // per-chunk max of dual

__device__ __forceinline__ float ex2(float x) {
    float y; asm("ex2.approx.f32 %0, %1;" : "=f"(y) : "f"(x)); return y;
}

__device__ __forceinline__ unsigned expand10(unsigned v) {
    v &= 1023u;
    v = (v | (v << 16)) & 0x030000FFu;
    v = (v | (v << 8))  & 0x0300F00Fu;
    v = (v | (v << 4))  & 0x030C30C3u;
    v = (v | (v << 2))  & 0x09249249u;
    return v;
}

__global__ void key_kernel(const float* __restrict__ X, const float* __restrict__ Y) {
    int i = blockIdx.x * blockDim.x + threadIdx.x;
    if (i >= NPT) return;
    const float* P[2] = {X, Y};
#pragma unroll
    for (int s = 0; s < 2; s++) {
        float x0 = P[s][3*i], x1 = P[s][3*i+1], x2 = P[s][3*i+2];
        unsigned qx = min(1023, max(0, (int)(x0 * 1024.f)));
        unsigned qy = min(1023, max(0, (int)(x1 * 1024.f)));
        unsigned qz = min(1023, max(0, (int)(x2 * 1024.f)));
        u64 code = expand10(qx) | (expand10(qy) << 1) | (expand10(qz) << 2);
        d_keys[s][i] = (code << 13) | (u64)i;
    }
}

__global__ void sort_kernel() {
    u64* keys = d_keys[blockIdx.x];
    for (int k = 2; k <= NPT; k <<= 1) {
        for (int j = k >> 1; j > 0; j >>= 1) {
            for (int t = threadIdx.x; t < NPT; t += blockDim.x) {
                int ixj = t ^ j;
                if (ixj > t) {
                    u64 a = keys[t], b = keys[ixj];
                    bool up = ((t & k) == 0);
                    if (up ? (a > b) : (a < b)) { keys[t] = b; keys[ixj] = a; }
                }
            }
            __syncthreads();
        }
    }
}

__global__ void build_kernel(const float* __restrict__ X, const float* __restrict__ Y) {
    int i = blockIdx.x * blockDim.x + threadIdx.x;
    if (i >= NPT) return;
    const float* P[2] = {X, Y};
#pragma unroll
    for (int s = 0; s < 2; s++) {
        int idx = (int)(d_keys[s][i] & 8191u);
        float x0 = P[s][3*idx], x1 = P[s][3*idx+1], x2 = P[s][3*idx+2];
        d_pts[s][i] = make_float4(x0, x1, x2, 0.5f * (x0*x0 + x1*x1 + x2*x2));
    }
#pragma unroll
    for (int p = 0; p < 4; p++) {
        d_du[0][p][i] = 0.f;
        d_ls[0][p][i] = K0 + 0.6f;
        if (i < NCHUNK) d_sU[0][p][i] = 0.f;
    }
}

__global__ void bbox_kernel() {
    int t = blockIdx.x * blockDim.x + threadIdx.x;
    if (t >= 2 * NCHUNK) return;
    int s = t >> 8, c = t & 255;
    float lx = 1e30f, ly = 1e30f, lz = 1e30f, hx = -1e30f, hy = -1e30f, hz = -1e30f;
#pragma unroll 8
    for (int j = 0; j < 32; j++) {
        float4 p = d_pts[s][c * 32 + j];
        lx = fminf(lx, p.x); ly = fminf(ly, p.y); lz = fminf(lz, p.z);
        hx = fmaxf(hx, p.x); hy = fmaxf(hy, p.y); hz = fmaxf(hz, p.z);
    }
    d_bLo[s][c] = make_float4(lx, ly, lz, 0.f);
    d_bHi[s][c] = make_float4(hx, hy, hz, 0.f);
}

// One launch = one Sinkhorn phase; one-pass softmin with prologue-computed
// per-warp skip masks. useCta=1 (sc<=64): CTA-uniform M folded into staging,
// inner loop has no per-element shift FADD. useCta=0: per-row M (R6 path).
__global__ void __launch_bounds__(THREADS)
phase_kernel(float eps, float ratio_inv, int avg, int par, int useCta) {
    __shared__ float4   tile[TILE];
    __shared__ unsigned smask[4][NTILE];
    __shared__ float    shRes[ROWS_CTA];
    __shared__ float    shM[4];

    int prob = blockIdx.x >> 8;
    int rb   = blockIdx.x & (CTA_PER_PROB - 1);

    int cset = (prob == 1 || prob == 2) ? 0 : 1;
    int rset = (prob == 0 || prob == 2) ? 0 : 1;
    const float4* __restrict__ cpts = d_pts[cset];
    const float4* __restrict__ rpts = d_pts[rset];
    int didx = (prob == 0) ? 1 : (prob == 1) ? 0 : prob;
    const float* __restrict__ cdual  = d_du[par][didx];
    const float* __restrict__ oldpot = d_du[par][prob];
    const float* __restrict__ oldlse = d_ls[par][prob];
    const float* __restrict__ sUraw  = d_sU[par][didx];
    float* __restrict__ outpot       = d_du[par ^ 1][prob];
    float* __restrict__ outlse       = d_ls[par ^ 1][prob];

    int warp = threadIdx.x >> 5;
    int lane = threadIdx.x & 31;
    int row0 = rb * ROWS_CTA + warp * RPW;

    float sc  = L2E / eps;
    float hsc = 0.5f * sc;

    float a0[RPW], a1[RPW], a2[RPW], NM[RPW], S[RPW];
    float rlx = 1e30f, rly = 1e30f, rlz = 1e30f;
    float rhx = -1e30f, rhy = -1e30f, rhz = -1e30f;
    float wM = -1e30f;                 // per-warp max of predicted per-row M
#pragma unroll
    for (int r = 0; r < RPW; r++) {
        float4 p = rpts[row0 + r];
        a0[r] = p.x * sc; a1[r] = p.y * sc; a2[r] = p.z * sc;
        float M = fmaf(oldlse[row0 + r] - K0, ratio_inv, K0 + 4.0f);
        NM[r] = -M;
        S[r] = 0.f;
        rlx = fminf(rlx, p.x); rly = fminf(rly, p.y); rlz = fminf(rlz, p.z);
        rhx = fmaxf(rhx, p.x); rhy = fmaxf(rhy, p.y); rhz = fmaxf(rhz, p.z);
        wM = fmaxf(wM, M);
    }
    if (lane == 0) shM[warp] = wM;

    __syncthreads();
    float Mcta = fmaxf(fmaxf(shM[0], shM[1]), fmaxf(shM[2], shM[3]));
    float cbk = K0;                    // constant added in staging
    if (useCta) {
        cbk = K0 - Mcta;               // fold CTA-uniform shift into staging
#pragma unroll
        for (int r = 0; r < RPW; r++) NM[r] = -Mcta;
    }

    float CRM = -1e30f;
#pragma unroll
    for (int r = 0; r < RPW; r++)
        CRM = fmaxf(CRM, fmaf(sc, rpts[row0 + r].w, NM[r]));

    // prologue: lane-parallel chunk tests -> 256-bit mask per warp
#pragma unroll
    for (int t8 = 0; t8 < NTILE; t8++) {
        int c = t8 * 32 + lane;
        float4 lo = d_bLo[cset][c];
        float4 hi = d_bHi[cset][c];
        float dx = fmaxf(0.f, fmaxf(lo.x - rhx, rlx - hi.x));
        float dy = fmaxf(0.f, fmaxf(lo.y - rhy, rly - hi.y));
        float dz = fmaxf(0.f, fmaxf(lo.z - rhz, rlz - hi.z));
        float mind2 = fmaf(dx, dx, fmaf(dy, dy, dz * dz));
        float UB = CRM + K0 + sc * sUraw[c] - hsc * mind2;
        unsigned b = __ballot_sync(0xffffffffu, UB >= THRESH);
        if (lane == 0) smask[warp][t8] = b;
    }
    __syncthreads();

    for (int t8 = 0; t8 < NTILE; t8++) {
        unsigned need = smask[0][t8] | smask[1][t8] | smask[2][t8] | smask[3][t8];
        if (!need) continue;
        __syncthreads();
        int tb = t8 * TILE;
        for (int j = threadIdx.x; j < TILE; j += THREADS) {
            float4 p = cpts[tb + j];
            p.w = fmaf(sc, cdual[tb + j] - p.w, cbk);
            tile[j] = p;
        }
        __syncthreads();

        unsigned mw = smask[warp][t8];
        if (useCta) {
            // lean loop: shift already folded into cc.w
            while (mw) {
                int k = __ffs(mw) - 1;
                mw &= mw - 1;
                float4 cc = tile[k * 32 + lane];
#pragma unroll
                for (int r = 0; r < RPW; r++) {
                    float t = fmaf(a0[r], cc.x,
                              fmaf(a1[r], cc.y,
                              fmaf(a2[r], cc.z, cc.w)));
                    S[r] += ex2(t);
                }
            }
        } else {
            while (mw) {
                int k = __ffs(mw) - 1;
                mw &= mw - 1;
                float4 cc = tile[k * 32 + lane];
#pragma unroll
                for (int r = 0; r < RPW; r++) {
                    float t = fmaf(a0[r], cc.x,
                              fmaf(a1[r], cc.y,
                              fmaf(a2[r], cc.z, cc.w + NM[r])));
                    S[r] += ex2(t);
                }
            }
        }
    }

#pragma unroll
    for (int r = 0; r < RPW; r++)
#pragma unroll
        for (int o = 16; o; o >>= 1)
            S[r] += __shfl_xor_sync(0xffffffffu, S[r], o);

    float lse[RPW];
    int bad = 0;
#pragma unroll
    for (int r = 0; r < RPW; r++) {
        if (!(S[r] > 1e-25f && S[r] < 1e25f)) bad = 1;
        lse[r] = -NM[r] + log2f(S[r]);
    }

    if (__any_sync(0xffffffffu, bad)) {
        // cold exact fallback: warp-local, no pruning, online softmax
#pragma unroll 1
        for (int r = 0; r < RPW; r++) {
            float4 q = rpts[row0 + r];
            float b0 = q.x * sc, b1 = q.y * sc, b2 = q.z * sc;
            float mm = -3.0e38f, ss = 0.f;
            for (int j = lane; j < NPT; j += 32) {
                float4 p = cpts[j];
                float t = fmaf(b0, p.x, fmaf(b1, p.y,
                          fmaf(b2, p.z, fmaf(sc, cdual[j] - p.w, K0))));
                float mn = fmaxf(mm, t);
                ss = fmaf(ss, ex2(mm - mn), ex2(t - mn));
                mm = mn;
            }
            for (int o = 16; o; o >>= 1) {
                float mo = __shfl_xor_sync(0xffffffffu, mm, o);
                float so = __shfl_xor_sync(0xffffffffu, ss, o);
                float mn = fmaxf(mm, mo);
                ss = ss * ex2(mm - mn) + so * ex2(mo - mn);
                mm = mn;
            }
            lse[r] = mm + log2f(ss);
        }
    }

    float resv[RPW];
#pragma unroll
    for (int r = 0; r < RPW; r++) {
        int row = row0 + r;
        float res = rpts[row].w - eps * LN2 * lse[r];
        resv[r] = avg ? 0.5f * (oldpot[row] + res) : res;
    }
    if (lane == 0) {
#pragma unroll
        for (int r = 0; r < RPW; r++) {
            int row = row0 + r;
            outpot[row] = resv[r];
            outlse[row] = lse[r];
            shRes[warp * RPW + r] = resv[r];
        }
    }
    __syncthreads();
    if (threadIdx.x < 32) {
        float v = shRes[threadIdx.x];
#pragma unroll
        for (int o = 16; o; o >>= 1)
            v = fmaxf(v, __shfl_xor_sync(0xffffffffu, v, o));
        if (threadIdx.x == 0) d_sU[par ^ 1][prob][rb] = v;
    }
}

__global__ void reduce_kernel(float* out, int out_size) {
    __shared__ double sh[256];
    double s = 0.0;
    for (int i = threadIdx.x; i < NPT; i += 256)
        s += (double)(d_du[1][0][i] - d_du[1][2][i])
           + (double)(d_du[1][1][i] - d_du[1][3][i]);
    sh[threadIdx.x] = s;
    __syncthreads();
    for (int o = 128; o > 0; o >>= 1) {
        if (threadIdx.x < o) sh[threadIdx.x] += sh[threadIdx.x + o];
        __syncthreads();
    }
    if (threadIdx.x == 0) {
        float v = (float)(sh[0] / (double)NPT);
        for (int k = 0; k < out_size; k++) out[k] = v;
    }
}

extern "C" void kernel_launch(void* const* d_in, const int* in_sizes, int n_in,
                              void* d_out, int out_size) {
    const float* X = (const float*)d_in[0];
    const float* Y = (const float*)d_in[1];

    double sched[96];
    int ns = 0;
    double e      = pow(2.0, 2.0);
    double target = pow(0.01, 2.0);
    double ratio  = pow(0.9, 2.0);
    while (e > target) { sched[ns++] = e; e *= ratio; }

    key_kernel<<<NPT / 256, 256>>>(X, Y);
    sort_kernel<<<2, 1024>>>();
    build_kernel<<<NPT / 256, 256>>>(X, Y);
    bbox_kernel<<<2, 256>>>();

    double eps_prev = sched[0];
    for (int p = 0; p <= ns + 1; p++) {
        double eps; int avg;
        if (p == 0)       { eps = sched[0];     avg = 0; }
        else if (p <= ns) { eps = sched[p - 1]; avg = 1; }
        else              { eps = target;       avg = 0; }
        float ratio_inv = (float)(eps_prev / eps);
        int useCta = ((double)L2E / eps <= (double)SC_CTAM) ? 1 : 0;
        phase_kernel<<<4 * CTA_PER_PROB, THREADS>>>((float)eps, ratio_inv, avg,
                                                    p & 1, useCta);
        eps_prev = eps;
    }
    reduce_kernel<<<1, 256>>>((float*)d_out, out_size);
}

// round 12
// speedup vs baseline: 1.4452x; 1.0976x over previous
#include <cuda_runtime.h>
#include <math.h>

#define NPT 8192
#define L2E 1.4426950408889634f
#define LN2 0.6931471805599453f
#define K0  (-13.0f)                 // log2(1/8192), exact

#define TILE 1024
#define RPW 8
#define THREADS 128
#define ROWS_CTA 32                   // 4 warps * 8 rows
#define CTA_PER_PROB 256              // NPT / ROWS_CTA
#define NCHUNK 256                    // NPT / 32
#define NTILE 8                       // NPT / TILE
#define THRESH (-35.0f)

typedef unsigned long long u64;

// Persistent scratch (no allocation anywhere)
__device__ u64    d_keys[2][NPT];
__device__ float4 d_pts[2][NPT];              // sorted: (x,y,z,|p|^2/2); 0=X,1=Y
__device__ float4 d_bLo[2][NCHUNK], d_bHi[2][NCHUNK];
__device__ float  d_du[2][4][NPT];            // [parity][f,g,pp,qq][sorted i]
__device__ float  d_ls[2][4][NPT];            // row lse (log2 units)
__device__ float  d_sU[2][4][NCHUNK];         // per-chunk max of dual

__device__ __forceinline__ float ex2(float x) {
    float y; asm("ex2.approx.f32 %0, %1;" : "=f"(y) : "f"(x)); return y;
}

__device__ __forceinline__ unsigned expand10(unsigned v) {
    v &= 1023u;
    v = (v | (v << 16)) & 0x030000FFu;
    v = (v | (v << 8))  & 0x0300F00Fu;
    v = (v | (v << 4))  & 0x030C30C3u;
    v = (v | (v << 2))  & 0x09249249u;
    return v;
}

__global__ void key_kernel(const float* __restrict__ X, const float* __restrict__ Y) {
    int i = blockIdx.x * blockDim.x + threadIdx.x;
    if (i >= NPT) return;
    const float* P[2] = {X, Y};
#pragma unroll
    for (int s = 0; s < 2; s++) {
        float x0 = P[s][3*i], x1 = P[s][3*i+1], x2 = P[s][3*i+2];
        unsigned qx = min(1023, max(0, (int)(x0 * 1024.f)));
        unsigned qy = min(1023, max(0, (int)(x1 * 1024.f)));
        unsigned qz = min(1023, max(0, (int)(x2 * 1024.f)));
        u64 code = expand10(qx) | (expand10(qy) << 1) | (expand10(qz) << 2);
        d_keys[s][i] = (code << 13) | (u64)i;
    }
}

__global__ void sort_kernel() {
    u64* keys = d_keys[blockIdx.x];
    for (int k = 2; k <= NPT; k <<= 1) {
        for (int j = k >> 1; j > 0; j >>= 1) {
            for (int t = threadIdx.x; t < NPT; t += blockDim.x) {
                int ixj = t ^ j;
                if (ixj > t) {
                    u64 a = keys[t], b = keys[ixj];
                    bool up = ((t & k) == 0);
                    if (up ? (a > b) : (a < b)) { keys[t] = b; keys[ixj] = a; }
                }
            }
            __syncthreads();
        }
    }
}

__global__ void build_kernel(const float* __restrict__ X, const float* __restrict__ Y) {
    int i = blockIdx.x * blockDim.x + threadIdx.x;
    if (i >= NPT) return;
    const float* P[2] = {X, Y};
#pragma unroll
    for (int s = 0; s < 2; s++) {
        int idx = (int)(d_keys[s][i] & 8191u);
        float x0 = P[s][3*idx], x1 = P[s][3*idx+1], x2 = P[s][3*idx+2];
        d_pts[s][i] = make_float4(x0, x1, x2, 0.5f * (x0*x0 + x1*x1 + x2*x2));
    }
#pragma unroll
    for (int p = 0; p < 4; p++) {
        d_du[0][p][i] = 0.f;
        d_ls[0][p][i] = K0 + 0.6f;
        if (i < NCHUNK) d_sU[0][p][i] = 0.f;
    }
}

__global__ void bbox_kernel() {
    int t = blockIdx.x * blockDim.x + threadIdx.x;
    if (t >= 2 * NCHUNK) return;
    int s = t >> 8, c = t & 255;
    float lx = 1e30f, ly = 1e30f, lz = 1e30f, hx = -1e30f, hy = -1e30f, hz = -1e30f;
#pragma unroll 8
    for (int j = 0; j < 32; j++) {
        float4 p = d_pts[s][c * 32 + j];
        lx = fminf(lx, p.x); ly = fminf(ly, p.y); lz = fminf(lz, p.z);
        hx = fmaxf(hx, p.x); hy = fmaxf(hy, p.y); hz = fmaxf(hz, p.z);
    }
    d_bLo[s][c] = make_float4(lx, ly, lz, 0.f);
    d_bHi[s][c] = make_float4(hx, hy, hz, 0.f);
}

// One launch = one Sinkhorn phase; one-pass softmin with prologue-computed
// per-warp skip masks (hot loop is branch-light and test-free).
// __launch_bounds__(128, 8): cap regs at 64 so all 1024 CTAs fit in one wave.
__global__ void __launch_bounds__(THREADS, 8)
phase_kernel(float eps, float ratio_inv, int avg, int par) {
    __shared__ float4   tile[TILE];
    __shared__ unsigned smask[4][NTILE];
    __shared__ float    shRes[ROWS_CTA];

    int prob = blockIdx.x >> 8;
    int rb   = blockIdx.x & (CTA_PER_PROB - 1);

    int cset = (prob == 1 || prob == 2) ? 0 : 1;
    int rset = (prob == 0 || prob == 2) ? 0 : 1;
    const float4* __restrict__ cpts = d_pts[cset];
    const float4* __restrict__ rpts = d_pts[rset];
    int didx = (prob == 0) ? 1 : (prob == 1) ? 0 : prob;
    const float* __restrict__ cdual  = d_du[par][didx];
    const float* __restrict__ oldpot = d_du[par][prob];
    const float* __restrict__ oldlse = d_ls[par][prob];
    const float* __restrict__ sUraw  = d_sU[par][didx];
    float* __restrict__ outpot       = d_du[par ^ 1][prob];
    float* __restrict__ outlse       = d_ls[par ^ 1][prob];

    int warp = threadIdx.x >> 5;
    int lane = threadIdx.x & 31;
    int row0 = rb * ROWS_CTA + warp * RPW;

    float sc  = L2E / eps;
    float hsc = 0.5f * sc;

    float a0[RPW], a1[RPW], a2[RPW], NM[RPW], S[RPW];

    {   // prologue scope: bbox / CRM / mask temporaries die before the hot loop
        float rlx = 1e30f, rly = 1e30f, rlz = 1e30f;
        float rhx = -1e30f, rhy = -1e30f, rhz = -1e30f;
        float CRM = -1e30f;
#pragma unroll
        for (int r = 0; r < RPW; r++) {
            float4 p = rpts[row0 + r];
            a0[r] = p.x * sc; a1[r] = p.y * sc; a2[r] = p.z * sc;
            float M = fmaf(oldlse[row0 + r] - K0, ratio_inv, K0 + 4.0f);
            NM[r] = -M;
            S[r] = 0.f;
            rlx = fminf(rlx, p.x); rly = fminf(rly, p.y); rlz = fminf(rlz, p.z);
            rhx = fmaxf(rhx, p.x); rhy = fmaxf(rhy, p.y); rhz = fmaxf(rhz, p.z);
            CRM = fmaxf(CRM, sc * p.w - M);
        }

        // lane-parallel chunk tests -> 256-bit mask per warp (8 ballots)
#pragma unroll
        for (int t8 = 0; t8 < NTILE; t8++) {
            int c = t8 * 32 + lane;
            float4 lo = d_bLo[cset][c];
            float4 hi = d_bHi[cset][c];
            float dx = fmaxf(0.f, fmaxf(lo.x - rhx, rlx - hi.x));
            float dy = fmaxf(0.f, fmaxf(lo.y - rhy, rly - hi.y));
            float dz = fmaxf(0.f, fmaxf(lo.z - rhz, rlz - hi.z));
            float mind2 = fmaf(dx, dx, fmaf(dy, dy, dz * dz));
            float UB = CRM + K0 + sc * sUraw[c] - hsc * mind2;
            unsigned b = __ballot_sync(0xffffffffu, UB >= THRESH);
            if (lane == 0) smask[warp][t8] = b;
        }
    }
    __syncthreads();

    for (int t8 = 0; t8 < NTILE; t8++) {
        unsigned need = smask[0][t8] | smask[1][t8] | smask[2][t8] | smask[3][t8];
        if (!need) continue;                       // uniform across CTA
        __syncthreads();
        int tb = t8 * TILE;
        for (int j = threadIdx.x; j < TILE; j += THREADS) {
            float4 p = cpts[tb + j];
            p.w = fmaf(sc, cdual[tb + j] - p.w, K0);   // column bias cb_j
            tile[j] = p;
        }
        __syncthreads();

        unsigned mw = smask[warp][t8];
        while (mw) {
            int k = __ffs(mw) - 1;
            mw &= mw - 1;
            float4 cc = tile[k * 32 + lane];
#pragma unroll
            for (int r = 0; r < RPW; r++) {
                float t = fmaf(a0[r], cc.x,
                          fmaf(a1[r], cc.y,
                          fmaf(a2[r], cc.z, cc.w + NM[r])));
                S[r] += ex2(t);
            }
        }
    }

    // warp reduce sums (M warp-uniform per row)
#pragma unroll
    for (int r = 0; r < RPW; r++)
#pragma unroll
        for (int o = 16; o; o >>= 1)
            S[r] += __shfl_xor_sync(0xffffffffu, S[r], o);

    float lse[RPW];
    int bad = 0;
#pragma unroll
    for (int r = 0; r < RPW; r++) {
        if (!(S[r] > 1e-25f && S[r] < 1e25f)) bad = 1;
        lse[r] = -NM[r] + log2f(S[r]);
    }

    if (__any_sync(0xffffffffu, bad)) {
        // cold exact fallback: warp-local, no pruning, online softmax
#pragma unroll 1
        for (int r = 0; r < RPW; r++) {
            float4 q = rpts[row0 + r];
            float b0 = q.x * sc, b1 = q.y * sc, b2 = q.z * sc;
            float mm = -3.0e38f, ss = 0.f;
            for (int j = lane; j < NPT; j += 32) {
                float4 p = cpts[j];
                float t = fmaf(b0, p.x, fmaf(b1, p.y,
                          fmaf(b2, p.z, fmaf(sc, cdual[j] - p.w, K0))));
                float mn = fmaxf(mm, t);
                ss = fmaf(ss, ex2(mm - mn), ex2(t - mn));
                mm = mn;
            }
            for (int o = 16; o; o >>= 1) {
                float mo = __shfl_xor_sync(0xffffffffu, mm, o);
                float so = __shfl_xor_sync(0xffffffffu, ss, o);
                float mn = fmaxf(mm, mo);
                ss = ss * ex2(mm - mn) + so * ex2(mo - mn);
                mm = mn;
            }
            lse[r] = mm + log2f(ss);
        }
    }

    // epilogue: write potentials + lse; fold per-chunk dual max into d_sU
    float resv[RPW];
#pragma unroll
    for (int r = 0; r < RPW; r++) {
        int row = row0 + r;
        float res = rpts[row].w - eps * LN2 * lse[r];
        resv[r] = avg ? 0.5f * (oldpot[row] + res) : res;
    }
    if (lane == 0) {
#pragma unroll
        for (int r = 0; r < RPW; r++) {
            int row = row0 + r;
            outpot[row] = resv[r];
            outlse[row] = lse[r];
            shRes[warp * RPW + r] = resv[r];
        }
    }
    __syncthreads();
    if (threadIdx.x < 32) {
        float v = shRes[threadIdx.x];
#pragma unroll
        for (int o = 16; o; o >>= 1)
            v = fmaxf(v, __shfl_xor_sync(0xffffffffu, v, o));
        if (threadIdx.x == 0) d_sU[par ^ 1][prob][rb] = v;
    }
}

__global__ void reduce_kernel(float* out, int out_size) {
    __shared__ double sh[256];
    double s = 0.0;
    for (int i = threadIdx.x; i < NPT; i += 256)
        s += (double)(d_du[1][0][i] - d_du[1][2][i])
           + (double)(d_du[1][1][i] - d_du[1][3][i]);
    sh[threadIdx.x] = s;
    __syncthreads();
    for (int o = 128; o > 0; o >>= 1) {
        if (threadIdx.x < o) sh[threadIdx.x] += sh[threadIdx.x + o];
        __syncthreads();
    }
    if (threadIdx.x == 0) {
        float v = (float)(sh[0] / (double)NPT);
        for (int k = 0; k < out_size; k++) out[k] = v;
    }
}

extern "C" void kernel_launch(void* const* d_in, const int* in_sizes, int n_in,
                              void* d_out, int out_size) {
    const float* X = (const float*)d_in[0];
    const float* Y = (const float*)d_in[1];

    double sched[96];
    int ns = 0;
    double e      = pow(2.0, 2.0);
    double target = pow(0.01, 2.0);
    double ratio  = pow(0.9, 2.0);
    while (e > target) { sched[ns++] = e; e *= ratio; }

    key_kernel<<<NPT / 256, 256>>>(X, Y);
    sort_kernel<<<2, 1024>>>();
    build_kernel<<<NPT / 256, 256>>>(X, Y);
    bbox_kernel<<<2, 256>>>();

    double eps_prev = sched[0];
    for (int p = 0; p <= ns + 1; p++) {
        double eps; int avg;
        if (p == 0)       { eps = sched[0];     avg = 0; }
        else if (p <= ns) { eps = sched[p - 1]; avg = 1; }
        else              { eps = target;       avg = 0; }
        float ratio_inv = (float)(eps_prev / eps);
        phase_kernel<<<4 * CTA_PER_PROB, THREADS>>>((float)eps, ratio_inv, avg, p & 1);
        eps_prev = eps;
    }
    reduce_kernel<<<1, 256>>>((float*)d_out, out_size);
}

// round 13
// speedup vs baseline: 1.5184x; 1.0506x over previous
#include <cuda_runtime.h>
#include <math.h>

#define NPT 8192
#define L2E 1.4426950408889634f
#define LN2 0.6931471805599453f
#define K0  (-13.0f)                 // log2(1/8192), exact

#define TILE 1024
#define RPW 8
#define THREADS 128
#define ROWS_CTA 32                   // 4 warps * 8 rows
#define CTA_PER_PROB 256              // NPT / ROWS_CTA
#define NCHUNK 256                    // NPT / 32
#define NTILE 8                       // NPT / TILE
#define THRESH (-35.0f)
#define SC_LEAN 64.0f

typedef unsigned long long u64;

// Persistent scratch (no allocation anywhere)
__device__ u64    d_keys[2][NPT];
__device__ float4 d_pts[2][NPT];              // sorted: (x,y,z,|p|^2/2); 0=X,1=Y
__device__ float4 d_bLo[2][NCHUNK], d_bHi[2][NCHUNK];
__device__ float  d_du[2][4][NPT];            // [parity][f,g,pp,qq][sorted i]
__device__ float  d_ls[2][4][NPT];            // row lse (log2 units)
__device__ float  d_sU[2][4][NCHUNK];         // per-chunk max of dual

__device__ __forceinline__ float ex2(float x) {
    float y; asm("ex2.approx.f32 %0, %1;" : "=f"(y) : "f"(x)); return y;
}

__device__ __forceinline__ unsigned expand10(unsigned v) {
    v &= 1023u;
    v = (v | (v << 16)) & 0x030000FFu;
    v = (v | (v << 8))  & 0x0300F00Fu;
    v = (v | (v << 4))  & 0x030C30C3u;
    v = (v | (v << 2))  & 0x09249249u;
    return v;
}

__global__ void key_kernel(const float* __restrict__ X, const float* __restrict__ Y) {
    int i = blockIdx.x * blockDim.x + threadIdx.x;
    if (i >= NPT) return;
    const float* P[2] = {X, Y};
#pragma unroll
    for (int s = 0; s < 2; s++) {
        float x0 = P[s][3*i], x1 = P[s][3*i+1], x2 = P[s][3*i+2];
        unsigned qx = min(1023, max(0, (int)(x0 * 1024.f)));
        unsigned qy = min(1023, max(0, (int)(x1 * 1024.f)));
        unsigned qz = min(1023, max(0, (int)(x2 * 1024.f)));
        u64 code = expand10(qx) | (expand10(qy) << 1) | (expand10(qz) << 2);
        d_keys[s][i] = (code << 13) | (u64)i;
    }
}

__global__ void sort_kernel() {
    u64* keys = d_keys[blockIdx.x];
    for (int k = 2; k <= NPT; k <<= 1) {
        for (int j = k >> 1; j > 0; j >>= 1) {
            for (int t = threadIdx.x; t < NPT; t += blockDim.x) {
                int ixj = t ^ j;
                if (ixj > t) {
                    u64 a = keys[t], b = keys[ixj];
                    bool up = ((t & k) == 0);
                    if (up ? (a > b) : (a < b)) { keys[t] = b; keys[ixj] = a; }
                }
            }
            __syncthreads();
        }
    }
}

__global__ void build_kernel(const float* __restrict__ X, const float* __restrict__ Y) {
    int i = blockIdx.x * blockDim.x + threadIdx.x;
    if (i >= NPT) return;
    const float* P[2] = {X, Y};
#pragma unroll
    for (int s = 0; s < 2; s++) {
        int idx = (int)(d_keys[s][i] & 8191u);
        float x0 = P[s][3*idx], x1 = P[s][3*idx+1], x2 = P[s][3*idx+2];
        d_pts[s][i] = make_float4(x0, x1, x2, 0.5f * (x0*x0 + x1*x1 + x2*x2));
    }
#pragma unroll
    for (int p = 0; p < 4; p++) {
        d_du[0][p][i] = 0.f;
        d_ls[0][p][i] = K0 + 0.6f;
        if (i < NCHUNK) d_sU[0][p][i] = 0.f;
    }
}

__global__ void bbox_kernel() {
    int t = blockIdx.x * blockDim.x + threadIdx.x;
    if (t >= 2 * NCHUNK) return;
    int s = t >> 8, c = t & 255;
    float lx = 1e30f, ly = 1e30f, lz = 1e30f, hx = -1e30f, hy = -1e30f, hz = -1e30f;
#pragma unroll 8
    for (int j = 0; j < 32; j++) {
        float4 p = d_pts[s][c * 32 + j];
        lx = fminf(lx, p.x); ly = fminf(ly, p.y); lz = fminf(lz, p.z);
        hx = fmaxf(hx, p.x); hy = fmaxf(hy, p.y); hz = fmaxf(hz, p.z);
    }
    d_bLo[s][c] = make_float4(lx, ly, lz, 0.f);
    d_bHi[s][c] = make_float4(hx, hy, hz, 0.f);
}

// One launch = one Sinkhorn phase; one-pass softmin with prologue-computed
// per-warp skip masks (per-row M -> pruning is sound per row).
// lean=1 (sc<=64): accumulation shifted by CTA-uniform Mcta folded into the
// staged column bias (inner loop has no per-element shift FADD); lse rescaled
// by Mcta at the end. Pure refactoring of scaling -- no truncation change.
__global__ void __launch_bounds__(THREADS, 8)
phase_kernel(float eps, float ratio_inv, int avg, int par, int lean) {
    __shared__ float4   tile[TILE];
    __shared__ unsigned smask[4][NTILE];
    __shared__ float    shRes[ROWS_CTA];
    __shared__ float    shM[4];

    int prob = blockIdx.x >> 8;
    int rb   = blockIdx.x & (CTA_PER_PROB - 1);

    int cset = (prob == 1 || prob == 2) ? 0 : 1;
    int rset = (prob == 0 || prob == 2) ? 0 : 1;
    const float4* __restrict__ cpts = d_pts[cset];
    const float4* __restrict__ rpts = d_pts[rset];
    int didx = (prob == 0) ? 1 : (prob == 1) ? 0 : prob;
    const float* __restrict__ cdual  = d_du[par][didx];
    const float* __restrict__ oldpot = d_du[par][prob];
    const float* __restrict__ oldlse = d_ls[par][prob];
    const float* __restrict__ sUraw  = d_sU[par][didx];
    float* __restrict__ outpot       = d_du[par ^ 1][prob];
    float* __restrict__ outlse       = d_ls[par ^ 1][prob];

    int warp = threadIdx.x >> 5;
    int lane = threadIdx.x & 31;
    int row0 = rb * ROWS_CTA + warp * RPW;

    float sc  = L2E / eps;
    float hsc = 0.5f * sc;

    float a0[RPW], a1[RPW], a2[RPW], NM[RPW], S[RPW];

    {   // prologue scope: temporaries die before the hot loop
        float rlx = 1e30f, rly = 1e30f, rlz = 1e30f;
        float rhx = -1e30f, rhy = -1e30f, rhz = -1e30f;
        float CRM = -1e30f, wM = -1e30f;
#pragma unroll
        for (int r = 0; r < RPW; r++) {
            float4 p = rpts[row0 + r];
            a0[r] = p.x * sc; a1[r] = p.y * sc; a2[r] = p.z * sc;
            float M = fmaf(oldlse[row0 + r] - K0, ratio_inv, K0 + 4.0f);
            NM[r] = -M;
            S[r] = 0.f;
            rlx = fminf(rlx, p.x); rly = fminf(rly, p.y); rlz = fminf(rlz, p.z);
            rhx = fmaxf(rhx, p.x); rhy = fmaxf(rhy, p.y); rhz = fmaxf(rhz, p.z);
            CRM = fmaxf(CRM, sc * p.w - M);    // per-row M: sound pruning
            wM  = fmaxf(wM, M);
        }
        if (lane == 0) shM[warp] = wM;

        // lane-parallel chunk tests -> 256-bit mask per warp (8 ballots)
#pragma unroll
        for (int t8 = 0; t8 < NTILE; t8++) {
            int c = t8 * 32 + lane;
            float4 lo = d_bLo[cset][c];
            float4 hi = d_bHi[cset][c];
            float dx = fmaxf(0.f, fmaxf(lo.x - rhx, rlx - hi.x));
            float dy = fmaxf(0.f, fmaxf(lo.y - rhy, rly - hi.y));
            float dz = fmaxf(0.f, fmaxf(lo.z - rhz, rlz - hi.z));
            float mind2 = fmaf(dx, dx, fmaf(dy, dy, dz * dz));
            float UB = CRM + K0 + sc * sUraw[c] - hsc * mind2;
            unsigned b = __ballot_sync(0xffffffffu, UB >= THRESH);
            if (lane == 0) smask[warp][t8] = b;
        }
    }
    __syncthreads();

    float Mcta = fmaxf(fmaxf(shM[0], shM[1]), fmaxf(shM[2], shM[3]));
    float cbk  = lean ? (K0 - Mcta) : K0;     // constant folded into staging

    for (int t8 = 0; t8 < NTILE; t8++) {
        unsigned need = smask[0][t8] | smask[1][t8] | smask[2][t8] | smask[3][t8];
        if (!need) continue;                       // uniform across CTA
        __syncthreads();
        int tb = t8 * TILE;
        for (int j = threadIdx.x; j < TILE; j += THREADS) {
            float4 p = cpts[tb + j];
            p.w = fmaf(sc, cdual[tb + j] - p.w, cbk);   // column bias cb_j
            tile[j] = p;
        }
        __syncthreads();

        unsigned mw = smask[warp][t8];
        if (lean) {
            while (mw) {                 // shift pre-folded: 4 fixed ops + MUFU
                int k = __ffs(mw) - 1;
                mw &= mw - 1;
                float4 cc = tile[k * 32 + lane];
#pragma unroll
                for (int r = 0; r < RPW; r++) {
                    float t = fmaf(a0[r], cc.x,
                              fmaf(a1[r], cc.y,
                              fmaf(a2[r], cc.z, cc.w)));
                    S[r] += ex2(t);
                }
            }
        } else {
            while (mw) {
                int k = __ffs(mw) - 1;
                mw &= mw - 1;
                float4 cc = tile[k * 32 + lane];
#pragma unroll
                for (int r = 0; r < RPW; r++) {
                    float t = fmaf(a0[r], cc.x,
                              fmaf(a1[r], cc.y,
                              fmaf(a2[r], cc.z, cc.w + NM[r])));
                    S[r] += ex2(t);
                }
            }
        }
    }

    // warp reduce sums (shift warp-uniform per row in both paths)
#pragma unroll
    for (int r = 0; r < RPW; r++)
#pragma unroll
        for (int o = 16; o; o >>= 1)
            S[r] += __shfl_xor_sync(0xffffffffu, S[r], o);

    float lse[RPW];
    int bad = 0;
#pragma unroll
    for (int r = 0; r < RPW; r++) {
        if (!(S[r] > 1e-25f && S[r] < 1e25f)) bad = 1;
        float shift = lean ? Mcta : -NM[r];
        lse[r] = shift + log2f(S[r]);
    }

    if (__any_sync(0xffffffffu, bad)) {
        // cold exact fallback: warp-local, no pruning, online softmax
#pragma unroll 1
        for (int r = 0; r < RPW; r++) {
            float4 q = rpts[row0 + r];
            float b0 = q.x * sc, b1 = q.y * sc, b2 = q.z * sc;
            float mm = -3.0e38f, ss = 0.f;
            for (int j = lane; j < NPT; j += 32) {
                float4 p = cpts[j];
                float t = fmaf(b0, p.x, fmaf(b1, p.y,
                          fmaf(b2, p.z, fmaf(sc, cdual[j] - p.w, K0))));
                float mn = fmaxf(mm, t);
                ss = fmaf(ss, ex2(mm - mn), ex2(t - mn));
                mm = mn;
            }
            for (int o = 16; o; o >>= 1) {
                float mo = __shfl_xor_sync(0xffffffffu, mm, o);
                float so = __shfl_xor_sync(0xffffffffu, ss, o);
                float mn = fmaxf(mm, mo);
                ss = ss * ex2(mm - mn) + so * ex2(mo - mn);
                mm = mn;
            }
            lse[r] = mm + log2f(ss);
        }
    }

    // epilogue: write potentials + lse; fold per-chunk dual max into d_sU
    float resv[RPW];
#pragma unroll
    for (int r = 0; r < RPW; r++) {
        int row = row0 + r;
        float res = rpts[row].w - eps * LN2 * lse[r];
        resv[r] = avg ? 0.5f * (oldpot[row] + res) : res;
    }
    if (lane == 0) {
#pragma unroll
        for (int r = 0; r < RPW; r++) {
            int row = row0 + r;
            outpot[row] = resv[r];
            outlse[row] = lse[r];
            shRes[warp * RPW + r] = resv[r];
        }
    }
    __syncthreads();
    if (threadIdx.x < 32) {
        float v = shRes[threadIdx.x];
#pragma unroll
        for (int o = 16; o; o >>= 1)
            v = fmaxf(v, __shfl_xor_sync(0xffffffffu, v, o));
        if (threadIdx.x == 0) d_sU[par ^ 1][prob][rb] = v;
    }
}

__global__ void reduce_kernel(float* out, int out_size) {
    __shared__ double sh[256];
    double s = 0.0;
    for (int i = threadIdx.x; i < NPT; i += 256)
        s += (double)(d_du[1][0][i] - d_du[1][2][i])
           + (double)(d_du[1][1][i] - d_du[1][3][i]);
    sh[threadIdx.x] = s;
    __syncthreads();
    for (int o = 128; o > 0; o >>= 1) {
        if (threadIdx.x < o) sh[threadIdx.x] += sh[threadIdx.x + o];
        __syncthreads();
    }
    if (threadIdx.x == 0) {
        float v = (float)(sh[0] / (double)NPT);
        for (int k = 0; k < out_size; k++) out[k] = v;
    }
}

extern "C" void kernel_launch(void* const* d_in, const int* in_sizes, int n_in,
                              void* d_out, int out_size) {
    const float* X = (const float*)d_in[0];
    const float* Y = (const float*)d_in[1];

    double sched[96];
    int ns = 0;
    double e      = pow(2.0, 2.0);
    double target = pow(0.01, 2.0);
    double ratio  = pow(0.9, 2.0);
    while (e > target) { sched[ns++] = e; e *= ratio; }

    key_kernel<<<NPT / 256, 256>>>(X, Y);
    sort_kernel<<<2, 1024>>>();
    build_kernel<<<NPT / 256, 256>>>(X, Y);
    bbox_kernel<<<2, 256>>>();

    double eps_prev = sched[0];
    for (int p = 0; p <= ns + 1; p++) {
        double eps; int avg;
        if (p == 0)       { eps = sched[0];     avg = 0; }
        else if (p <= ns) { eps = sched[p - 1]; avg = 1; }
        else              { eps = target;       avg = 0; }
        float ratio_inv = (float)(eps_prev / eps);
        int lean = ((double)L2E / eps <= (double)SC_LEAN) ? 1 : 0;
        phase_kernel<<<4 * CTA_PER_PROB, THREADS>>>((float)eps, ratio_inv, avg,
                                                    p & 1, lean);
        eps_prev = eps;
    }
    reduce_kernel<<<1, 256>>>((float*)d_out, out_size);
}

// round 15
// speedup vs baseline: 1.6142x; 1.0631x over previous
#include <cuda_runtime.h>
#include <math.h>

#define NPT 8192
#define L2E 1.4426950408889634f
#define LN2 0.6931471805599453f
#define K0  (-13.0f)                 // log2(1/8192), exact

#define TILE 1024
#define RPW 8
#define THREADS 128
#define ROWS_CTA 32                   // 4 warps * 8 rows
#define CTA_PER_PROB 256              // NPT / ROWS_CTA
#define NCHUNK 256                    // NPT / 32
#define NTILE 8                       // NPT / TILE
#define THRESH (-35.0f)
#define SC_LEAN 64.0f

typedef unsigned long long u64;

// Persistent scratch (no allocation anywhere)
__device__ u64    d_keys[2][NPT];
__device__ float4 d_pts[2][NPT];              // sorted: (x,y,z,|p|^2/2); 0=X,1=Y
__device__ float4 d_bLo[2][NCHUNK], d_bHi[2][NCHUNK];
__device__ float  d_du[2][4][NPT];            // [parity][f,g,pp,qq][sorted i]
__device__ float  d_ls[2][4][NPT];            // row lse (log2 units)
__device__ float  d_sU[2][4][NCHUNK];         // per-chunk max of dual

__device__ __forceinline__ float ex2(float x) {
    float y; asm("ex2.approx.f32 %0, %1;" : "=f"(y) : "f"(x)); return y;
}

__device__ __forceinline__ unsigned expand10(unsigned v) {
    v &= 1023u;
    v = (v | (v << 16)) & 0x030000FFu;
    v = (v | (v << 8))  & 0x0300F00Fu;
    v = (v | (v << 4))  & 0x030C30C3u;
    v = (v | (v << 2))  & 0x09249249u;
    return v;
}

__global__ void key_kernel(const float* __restrict__ X, const float* __restrict__ Y) {
    int i = blockIdx.x * blockDim.x + threadIdx.x;
    if (i >= NPT) return;
    const float* P[2] = {X, Y};
#pragma unroll
    for (int s = 0; s < 2; s++) {
        float x0 = P[s][3*i], x1 = P[s][3*i+1], x2 = P[s][3*i+2];
        unsigned qx = min(1023, max(0, (int)(x0 * 1024.f)));
        unsigned qy = min(1023, max(0, (int)(x1 * 1024.f)));
        unsigned qz = min(1023, max(0, (int)(x2 * 1024.f)));
        u64 code = expand10(qx) | (expand10(qy) << 1) | (expand10(qz) << 2);
        d_keys[s][i] = (code << 13) | (u64)i;
    }
}

__global__ void sort_kernel() {
    u64* keys = d_keys[blockIdx.x];
    for (int k = 2; k <= NPT; k <<= 1) {
        for (int j = k >> 1; j > 0; j >>= 1) {
            for (int t = threadIdx.x; t < NPT; t += blockDim.x) {
                int ixj = t ^ j;
                if (ixj > t) {
                    u64 a = keys[t], b = keys[ixj];
                    bool up = ((t & k) == 0);
                    if (up ? (a > b) : (a < b)) { keys[t] = b; keys[ixj] = a; }
                }
            }
            __syncthreads();
        }
    }
}

__global__ void build_kernel(const float* __restrict__ X, const float* __restrict__ Y) {
    int i = blockIdx.x * blockDim.x + threadIdx.x;
    if (i >= NPT) return;
    const float* P[2] = {X, Y};
#pragma unroll
    for (int s = 0; s < 2; s++) {
        int idx = (int)(d_keys[s][i] & 8191u);
        float x0 = P[s][3*idx], x1 = P[s][3*idx+1], x2 = P[s][3*idx+2];
        d_pts[s][i] = make_float4(x0, x1, x2, 0.5f * (x0*x0 + x1*x1 + x2*x2));
    }
#pragma unroll
    for (int p = 0; p < 4; p++) {
        d_du[0][p][i] = 0.f;
        d_ls[0][p][i] = K0 + 0.6f;
        if (i < NCHUNK) d_sU[0][p][i] = 0.f;
    }
}

__global__ void bbox_kernel() {
    int t = blockIdx.x * blockDim.x + threadIdx.x;
    if (t >= 2 * NCHUNK) return;
    int s = t >> 8, c = t & 255;
    float lx = 1e30f, ly = 1e30f, lz = 1e30f, hx = -1e30f, hy = -1e30f, hz = -1e30f;
#pragma unroll 8
    for (int j = 0; j < 32; j++) {
        float4 p = d_pts[s][c * 32 + j];
        lx = fminf(lx, p.x); ly = fminf(ly, p.y); lz = fminf(lz, p.z);
        hx = fmaxf(hx, p.x); hy = fmaxf(hy, p.y); hz = fmaxf(hz, p.z);
    }
    d_bLo[s][c] = make_float4(lx, ly, lz, 0.f);
    d_bHi[s][c] = make_float4(hx, hy, hz, 0.f);
}

// inner-loop bodies (identical math to R10; dispatch differs only in looping)
#define BODY_LEAN(kk)                                                         \
    {                                                                         \
        float4 cc = tile[(kk) * 32 + lane];                                   \
        _Pragma("unroll")                                                     \
        for (int r = 0; r < RPW; r++) {                                       \
            float t = fmaf(a0[r], cc.x,                                       \
                      fmaf(a1[r], cc.y,                                       \
                      fmaf(a2[r], cc.z, cc.w)));                              \
            S[r] += ex2(t);                                                   \
        }                                                                     \
    }

#define BODY_ROW(kk)                                                          \
    {                                                                         \
        float4 cc = tile[(kk) * 32 + lane];                                   \
        _Pragma("unroll")                                                     \
        for (int r = 0; r < RPW; r++) {                                       \
            float t = fmaf(a0[r], cc.x,                                       \
                      fmaf(a1[r], cc.y,                                       \
                      fmaf(a2[r], cc.z, cc.w + NM[r])));                      \
            S[r] += ex2(t);                                                   \
        }                                                                     \
    }

// One launch = one Sinkhorn phase; one-pass softmin with prologue-computed
// per-warp skip masks (per-row M -> pruning is sound per row).
// lean=1 (sc<=64): CTA-uniform Mcta folded into staged bias.
// Full-mask tiles take a straight-line unrolled path (no ffs/branch per chunk).
__global__ void __launch_bounds__(THREADS, 8)
phase_kernel(float eps, float ratio_inv, int avg, int par, int lean) {
    __shared__ float4   tile[TILE];
    __shared__ unsigned smask[4][NTILE];
    __shared__ float    shRes[ROWS_CTA];
    __shared__ float    shM[4];

    int prob = blockIdx.x >> 8;
    int rb   = blockIdx.x & (CTA_PER_PROB - 1);

    int cset = (prob == 1 || prob == 2) ? 0 : 1;
    int rset = (prob == 0 || prob == 2) ? 0 : 1;
    const float4* __restrict__ cpts = d_pts[cset];
    const float4* __restrict__ rpts = d_pts[rset];
    int didx = (prob == 0) ? 1 : (prob == 1) ? 0 : prob;
    const float* __restrict__ cdual  = d_du[par][didx];
    const float* __restrict__ oldpot = d_du[par][prob];
    const float* __restrict__ oldlse = d_ls[par][prob];
    const float* __restrict__ sUraw  = d_sU[par][didx];
    float* __restrict__ outpot       = d_du[par ^ 1][prob];
    float* __restrict__ outlse       = d_ls[par ^ 1][prob];

    int warp = threadIdx.x >> 5;
    int lane = threadIdx.x & 31;
    int row0 = rb * ROWS_CTA + warp * RPW;

    float sc  = L2E / eps;
    float hsc = 0.5f * sc;

    float a0[RPW], a1[RPW], a2[RPW], NM[RPW], S[RPW];

    {   // prologue scope: temporaries die before the hot loop
        float rlx = 1e30f, rly = 1e30f, rlz = 1e30f;
        float rhx = -1e30f, rhy = -1e30f, rhz = -1e30f;
        float CRM = -1e30f, wM = -1e30f;
#pragma unroll
        for (int r = 0; r < RPW; r++) {
            float4 p = rpts[row0 + r];
            a0[r] = p.x * sc; a1[r] = p.y * sc; a2[r] = p.z * sc;
            float M = fmaf(oldlse[row0 + r] - K0, ratio_inv, K0 + 4.0f);
            NM[r] = -M;
            S[r] = 0.f;
            rlx = fminf(rlx, p.x); rly = fminf(rly, p.y); rlz = fminf(rlz, p.z);
            rhx = fmaxf(rhx, p.x); rhy = fmaxf(rhy, p.y); rhz = fmaxf(rhz, p.z);
            CRM = fmaxf(CRM, sc * p.w - M);    // per-row M: sound pruning
            wM  = fmaxf(wM, M);
        }
        if (lane == 0) shM[warp] = wM;

        // lane-parallel chunk tests -> 256-bit mask per warp (8 ballots)
#pragma unroll
        for (int t8 = 0; t8 < NTILE; t8++) {
            int c = t8 * 32 + lane;
            float4 lo = d_bLo[cset][c];
            float4 hi = d_bHi[cset][c];
            float dx = fmaxf(0.f, fmaxf(lo.x - rhx, rlx - hi.x));
            float dy = fmaxf(0.f, fmaxf(lo.y - rhy, rly - hi.y));
            float dz = fmaxf(0.f, fmaxf(lo.z - rhz, rlz - hi.z));
            float mind2 = fmaf(dx, dx, fmaf(dy, dy, dz * dz));
            float UB = CRM + K0 + sc * sUraw[c] - hsc * mind2;
            unsigned b = __ballot_sync(0xffffffffu, UB >= THRESH);
            if (lane == 0) smask[warp][t8] = b;
        }
    }
    __syncthreads();

    float Mcta = fmaxf(fmaxf(shM[0], shM[1]), fmaxf(shM[2], shM[3]));
    float cbk  = lean ? (K0 - Mcta) : K0;     // constant folded into staging

    for (int t8 = 0; t8 < NTILE; t8++) {
        unsigned need = smask[0][t8] | smask[1][t8] | smask[2][t8] | smask[3][t8];
        if (!need) continue;                       // uniform across CTA
        __syncthreads();
        int tb = t8 * TILE;
        for (int j = threadIdx.x; j < TILE; j += THREADS) {
            float4 p = cpts[tb + j];
            p.w = fmaf(sc, cdual[tb + j] - p.w, cbk);   // column bias cb_j
            tile[j] = p;
        }
        __syncthreads();

        unsigned mw = smask[warp][t8];
        if (lean) {
            if (mw == 0xffffffffu) {
#pragma unroll 4
                for (int k = 0; k < 32; k++) BODY_LEAN(k)
            } else {
                while (mw) {
                    int k = __ffs(mw) - 1;
                    mw &= mw - 1;
                    BODY_LEAN(k)
                }
            }
        } else {
            if (mw == 0xffffffffu) {
#pragma unroll 4
                for (int k = 0; k < 32; k++) BODY_ROW(k)
            } else {
                while (mw) {
                    int k = __ffs(mw) - 1;
                    mw &= mw - 1;
                    BODY_ROW(k)
                }
            }
        }
    }

    // warp reduce sums (shift warp-uniform per row in both paths)
#pragma unroll
    for (int r = 0; r < RPW; r++)
#pragma unroll
        for (int o = 16; o; o >>= 1)
            S[r] += __shfl_xor_sync(0xffffffffu, S[r], o);

    float lse[RPW];
    int bad = 0;
#pragma unroll
    for (int r = 0; r < RPW; r++) {
        if (!(S[r] > 1e-25f && S[r] < 1e25f)) bad = 1;
        float shift = lean ? Mcta : -NM[r];
        lse[r] = shift + log2f(S[r]);
    }

    if (__any_sync(0xffffffffu, bad)) {
        // cold exact fallback: warp-local, no pruning, online softmax
#pragma unroll 1
        for (int r = 0; r < RPW; r++) {
            float4 q = rpts[row0 + r];
            float b0 = q.x * sc, b1 = q.y * sc, b2 = q.z * sc;
            float mm = -3.0e38f, ss = 0.f;
            for (int j = lane; j < NPT; j += 32) {
                float4 p = cpts[j];
                float t = fmaf(b0, p.x, fmaf(b1, p.y,
                          fmaf(b2, p.z, fmaf(sc, cdual[j] - p.w, K0))));
                float mn = fmaxf(mm, t);
                ss = fmaf(ss, ex2(mm - mn), ex2(t - mn));
                mm = mn;
            }
            for (int o = 16; o; o >>= 1) {
                float mo = __shfl_xor_sync(0xffffffffu, mm, o);
                float so = __shfl_xor_sync(0xffffffffu, ss, o);
                float mn = fmaxf(mm, mo);
                ss = ss * ex2(mm - mn) + so * ex2(mo - mn);
                mm = mn;
            }
            lse[r] = mm + log2f(ss);
        }
    }

    // epilogue: write potentials + lse; fold per-chunk dual max into d_sU
    float resv[RPW];
#pragma unroll
    for (int r = 0; r < RPW; r++) {
        int row = row0 + r;
        float res = rpts[row].w - eps * LN2 * lse[r];
        resv[r] = avg ? 0.5f * (oldpot[row] + res) : res;
    }
    if (lane == 0) {
#pragma unroll
        for (int r = 0; r < RPW; r++) {
            int row = row0 + r;
            outpot[row] = resv[r];
            outlse[row] = lse[r];
            shRes[warp * RPW + r] = resv[r];
        }
    }
    __syncthreads();
    if (threadIdx.x < 32) {
        float v = shRes[threadIdx.x];
#pragma unroll
        for (int o = 16; o; o >>= 1)
            v = fmaxf(v, __shfl_xor_sync(0xffffffffu, v, o));
        if (threadIdx.x == 0) d_sU[par ^ 1][prob][rb] = v;
    }
}

__global__ void reduce_kernel(float* out, int out_size) {
    __shared__ double sh[256];
    double s = 0.0;
    for (int i = threadIdx.x; i < NPT; i += 256)
        s += (double)(d_du[1][0][i] - d_du[1][2][i])
           + (double)(d_du[1][1][i] - d_du[1][3][i]);
    sh[threadIdx.x] = s;
    __syncthreads();
    for (int o = 128; o > 0; o >>= 1) {
        if (threadIdx.x < o) sh[threadIdx.x] += sh[threadIdx.x + o];
        __syncthreads();
    }
    if (threadIdx.x == 0) {
        float v = (float)(sh[0] / (double)NPT);
        for (int k = 0; k < out_size; k++) out[k] = v;
    }
}

extern "C" void kernel_launch(void* const* d_in, const int* in_sizes, int n_in,
                              void* d_out, int out_size) {
    const float* X = (const float*)d_in[0];
    const float* Y = (const float*)d_in[1];

    double sched[96];
    int ns = 0;
    double e      = pow(2.0, 2.0);
    double target = pow(0.01, 2.0);
    double ratio  = pow(0.9, 2.0);
    while (e > target) { sched[ns++] = e; e *= ratio; }

    key_kernel<<<NPT / 256, 256>>>(X, Y);
    sort_kernel<<<2, 1024>>>();
    build_kernel<<<NPT / 256, 256>>>(X, Y);
    bbox_kernel<<<2, 256>>>();

    double eps_prev = sched[0];
    for (int p = 0; p <= ns + 1; p++) {
        double eps; int avg;
        if (p == 0)       { eps = sched[0];     avg = 0; }
        else if (p <= ns) { eps = sched[p - 1]; avg = 1; }
        else              { eps = target;       avg = 0; }
        float ratio_inv = (float)(eps_prev / eps);
        int lean = ((double)L2E / eps <= (double)SC_LEAN) ? 1 : 0;
        phase_kernel<<<4 * CTA_PER_PROB, THREADS>>>((float)eps, ratio_inv, avg,
                                                    p & 1, lean);
        eps_prev = eps;
    }
    reduce_kernel<<<1, 256>>>((float*)d_out, out_size);
}